// round 1
// baseline (speedup 1.0000x reference)
#include <cuda_runtime.h>
#include <cuda_bf16.h>

// Shapes (fixed): B=8, C=128, H=W=64, HW=4096, HWp=1024 (pooled), C8=16, C2=64.
#define Bb 8
#define Cc 128
#define HW 4096
#define HWP 1024
#define C8 16
#define C2 64

// Scratch (device globals; no allocation allowed)
__device__ float theta_g[Bb * C8 * HW];        // [b][c8][i]
__device__ float conv_g [Bb * 80 * HW];        // [b][cc(0..15=phi,16..79=g)][pix] pre-pool
__device__ float phi_g  [Bb * C8 * HWP];       // [b][c8][j]
__device__ float gsc_g  [Bb * HWP * C2];       // [b][j][c2]  (c2-contiguous for f32x2)

// ---------- packed f32x2 helpers ----------
__device__ __forceinline__ unsigned long long pk2(float a, float b) {
    unsigned long long r;
    asm("mov.b64 %0, {%1, %2};" : "=l"(r) : "f"(a), "f"(b));
    return r;
}
__device__ __forceinline__ unsigned long long fma2(unsigned long long a, unsigned long long b, unsigned long long c) {
    unsigned long long r;
    asm("fma.rn.f32x2 %0, %1, %2, %3;" : "=l"(r) : "l"(a), "l"(b), "l"(c));
    return r;
}
__device__ __forceinline__ unsigned long long mul2(unsigned long long a, unsigned long long b) {
    unsigned long long r;
    asm("mul.rn.f32x2 %0, %1, %2;" : "=l"(r) : "l"(a), "l"(b));
    return r;
}
__device__ __forceinline__ float2 upk2(unsigned long long a) {
    float2 r;
    asm("mov.b64 {%0, %1}, %2;" : "=f"(r.x), "=f"(r.y) : "l"(a));
    return r;
}

// ---------- Kernel 1: all 1x1 conv projections (theta full-res, phi/g full-res pre-pool) ----------
// grid (128, 6), block 256. gy=0: theta -> theta_g; gy=1: phi -> conv_g[0..15];
// gy=2..5: g rows (gy-2)*16.. -> conv_g[16+...]
__global__ void __launch_bounds__(256) proj_kernel(
    const float* __restrict__ x,
    const float* __restrict__ w_theta,
    const float* __restrict__ w_phi,
    const float* __restrict__ w_g)
{
    __shared__ __align__(16) float ws[C8 * Cc];   // 16x128
    int gy = blockIdx.y;
    const float* w;
    if (gy == 0)      w = w_theta;
    else if (gy == 1) w = w_phi;
    else              w = w_g + (gy - 2) * C8 * Cc;
    for (int idx = threadIdx.x; idx < C8 * Cc; idx += 256) ws[idx] = w[idx];
    __syncthreads();

    int t   = blockIdx.x * 256 + threadIdx.x;   // 0..32767
    int b   = t >> 12;
    int pix = t & (HW - 1);
    const float* xb = x + (size_t)b * Cc * HW + pix;

    unsigned long long acc[C8];
#pragma unroll
    for (int k = 0; k < C8; k++) acc[k] = 0ULL;

#pragma unroll 4
    for (int c = 0; c < Cc; c += 2) {
        float x0 = xb[(size_t)c * HW];
        float x1 = xb[(size_t)(c + 1) * HW];
        unsigned long long x2 = pk2(x0, x1);
#pragma unroll
        for (int k = 0; k < C8; k++) {
            const unsigned long long w2 = *(const unsigned long long*)&ws[k * Cc + c];
            acc[k] = fma2(w2, x2, acc[k]);
        }
    }

    float* dst;
    if (gy == 0) dst = theta_g + ((size_t)b * C8) * HW + pix;
    else         dst = conv_g  + ((size_t)b * 80 + (gy - 1) * 16) * HW + pix;
#pragma unroll
    for (int k = 0; k < C8; k++) {
        float2 v = upk2(acc[k]);
        dst[(size_t)k * HW] = v.x + v.y;
    }
}

// ---------- Kernel 2: 2x2 maxpool on phi/g pre-pool tensors ----------
// 8*80*1024 = 655360 outputs; grid 2560 x 256
__global__ void __launch_bounds__(256) pool_kernel()
{
    int t = blockIdx.x * 256 + threadIdx.x;
    int b   = t / (80 * HWP);
    int rem = t - b * (80 * HWP);
    int cc  = rem >> 10;
    int j   = rem & (HWP - 1);
    int py = j >> 5, px = j & 31;
    const float* src = conv_g + ((size_t)b * 80 + cc) * HW + py * 128 + px * 2;
    float m = fmaxf(fmaxf(src[0], src[1]), fmaxf(src[64], src[65]));
    if (cc < C8) phi_g[((size_t)b * C8 + cc) * HWP + j] = m;
    else         gsc_g[((size_t)b * HWP + j) * C2 + (cc - C8)] = m;
}

// ---------- Kernel 3: fused attention + output conv + residual ----------
// grid (16, 8), block 256, dyn smem 80KB.
// One thread per query index i. j streamed in 4 chunks of 256 through smem.
// No max-subtraction in softmax: |score| <~ 30 -> exp safely in fp32 range.
__global__ void __launch_bounds__(256, 2) attn_kernel(
    const float* __restrict__ x,
    const float* __restrict__ w_o,
    const float* __restrict__ gamma_p,
    float* __restrict__ out)
{
    extern __shared__ __align__(16) float sm[];
    float* phi_s = sm;            // [jl][16] : 4096 floats
    float* g_s   = sm + 4096;     // [jl][64] : 16384 floats (later reused for w_o)

    int b = blockIdx.y;
    int i = blockIdx.x * 256 + threadIdx.x;

    float th[C8];
#pragma unroll
    for (int k = 0; k < C8; k++) th[k] = theta_g[((size_t)b * C8 + k) * HW + i];

    unsigned long long acc[C2 / 2];
#pragma unroll
    for (int k = 0; k < C2 / 2; k++) acc[k] = 0ULL;
    float esum = 0.0f;

    for (int ch = 0; ch < 4; ch++) {
        int j0 = ch * 256;
        // load phi chunk transposed -> phi_s[jl][k]
        for (int idx = threadIdx.x; idx < C8 * 256; idx += 256) {
            int k = idx >> 8, jl = idx & 255;
            phi_s[jl * C8 + k] = phi_g[((size_t)b * C8 + k) * HWP + j0 + jl];
        }
        // load g chunk (already [j][c2]) with float4 copies
        {
            const float4* gsrc = (const float4*)(gsc_g + ((size_t)b * HWP + j0) * C2);
            float4* gdst = (float4*)g_s;
            for (int idx = threadIdx.x; idx < 256 * C2 / 4; idx += 256) gdst[idx] = gsrc[idx];
        }
        __syncthreads();

        for (int jl = 0; jl < 256; jl++) {
            const float4* pp = (const float4*)(phi_s + jl * C8);
            float4 p0 = pp[0], p1 = pp[1], p2 = pp[2], p3 = pp[3];
            // 4 parallel partial chains to shorten the dependency
            float sA = th[0] * p0.x;  sA = fmaf(th[4],  p1.x, sA);
            float sB = th[1] * p0.y;  sB = fmaf(th[5],  p1.y, sB);
            float sC = th[2] * p0.z;  sC = fmaf(th[6],  p1.z, sC);
            float sD = th[3] * p0.w;  sD = fmaf(th[7],  p1.w, sD);
            sA = fmaf(th[8],  p2.x, sA);  sA = fmaf(th[12], p3.x, sA);
            sB = fmaf(th[9],  p2.y, sB);  sB = fmaf(th[13], p3.y, sB);
            sC = fmaf(th[10], p2.z, sC);  sC = fmaf(th[14], p3.z, sC);
            sD = fmaf(th[11], p2.w, sD);  sD = fmaf(th[15], p3.w, sD);
            float s = (sA + sB) + (sC + sD);
            float e = __expf(s);
            esum += e;
            unsigned long long e2 = pk2(e, e);
            const unsigned long long* gj = (const unsigned long long*)(g_s + jl * C2);
#pragma unroll
            for (int k = 0; k < C2 / 2; k++) acc[k] = fma2(gj[k], e2, acc[k]);
        }
        __syncthreads();
    }

    float inv = 1.0f / esum;
    unsigned long long inv2 = pk2(inv, inv);
#pragma unroll
    for (int k = 0; k < C2 / 2; k++) acc[k] = mul2(acc[k], inv2);

    // load w_o [128][64] into g_s region
    for (int idx = threadIdx.x; idx < Cc * C2; idx += 256) g_s[idx] = w_o[idx];
    __syncthreads();

    float gamma = *gamma_p;
    const float* xb = x   + (size_t)b * Cc * HW + i;
    float*       ob = out + (size_t)b * Cc * HW + i;
#pragma unroll 4
    for (int co = 0; co < Cc; co++) {
        const unsigned long long* wo2 = (const unsigned long long*)(g_s + co * C2);
        unsigned long long r2 = 0ULL;
#pragma unroll
        for (int k = 0; k < C2 / 2; k++) r2 = fma2(wo2[k], acc[k], r2);
        float2 rv = upk2(r2);
        ob[(size_t)co * HW] = fmaf(gamma, rv.x + rv.y, xb[(size_t)co * HW]);
    }
}

extern "C" void kernel_launch(void* const* d_in, const int* in_sizes, int n_in,
                              void* d_out, int out_size)
{
    const float* x       = (const float*)d_in[0];
    const float* w_theta = (const float*)d_in[1];
    const float* w_phi   = (const float*)d_in[2];
    const float* w_g     = (const float*)d_in[3];
    const float* w_o     = (const float*)d_in[4];
    const float* gamma_p = (const float*)d_in[5];
    float* out = (float*)d_out;

    cudaFuncSetAttribute(attn_kernel, cudaFuncAttributeMaxDynamicSharedMemorySize, 80 * 1024);

    proj_kernel<<<dim3(128, 6), 256>>>(x, w_theta, w_phi, w_g);
    pool_kernel<<<2560, 256>>>();
    attn_kernel<<<dim3(16, 8), 256, 80 * 1024>>>(x, w_o, gamma_p, out);
}